// round 4
// baseline (speedup 1.0000x reference)
#include <cuda_runtime.h>

#define IMG_H 512
#define IMG_W 512
#define OUT_H 502
#define OUT_W 502
#define N_IMG 48
#define N_PIX (N_IMG * IMG_H * IMG_W)
#define N_OUT_D 12096192.0
#define TX 32
#define TY 22
#define IN_ROWS 32          // TY + 10
#define SP_W 44             // padded input-tile width (42 used)
#define H_ROWS 34           // 32 + 2 zero pad rows for the tail warp
#define H01_W 68            // 32 col-pairs (64 floats) + pad
#define H4_W 36
#define GRID_X 16
#define GRID_Y 23           // ceil(502/22)
#define TOTAL_BLOCKS (GRID_X * GRID_Y * N_IMG)

typedef unsigned long long ull;

__device__ double gSum = 0.0;
__device__ unsigned int gCount = 0u;
__device__ unsigned int gMaxKey = 0u;
__device__ unsigned int gMinKey = 0xFFFFFFFFu;

__device__ __forceinline__ unsigned int fkey(float f) {
    unsigned int u = __float_as_uint(f);
    return (u & 0x80000000u) ? ~u : (u | 0x80000000u);
}
__device__ __forceinline__ float funkey(unsigned int u) {
    return __uint_as_float((u & 0x80000000u) ? (u ^ 0x80000000u) : ~u);
}

// ---- packed f32x2 helpers (Blackwell FFMA2 path; ptxas never emits these from C++) ----
__device__ __forceinline__ ull pk2(float lo, float hi) {
    ull r;
    asm("mov.b64 %0, {%1, %2};" : "=l"(r) : "f"(lo), "f"(hi));
    return r;
}
__device__ __forceinline__ void upk2(float& lo, float& hi, ull v) {
    asm("mov.b64 {%0, %1}, %2;" : "=f"(lo), "=f"(hi) : "l"(v));
}
__device__ __forceinline__ ull mul2(ull a, ull b) {
    ull r;
    asm("mul.rn.f32x2 %0, %1, %2;" : "=l"(r) : "l"(a), "l"(b));
    return r;
}
__device__ __forceinline__ void fma2(ull& d, ull a, ull b) {
    asm("fma.rn.f32x2 %0, %1, %2, %0;" : "+l"(d) : "l"(a), "l"(b));
}

__global__ __launch_bounds__(256) void k_minmax(const float* __restrict__ x, int n) {
    float vmin = 3.4e38f, vmax = -3.4e38f;
    int idx = blockIdx.x * blockDim.x + threadIdx.x;
    int stride = gridDim.x * blockDim.x;
    int n4 = n >> 2;
    const float4* x4 = (const float4*)x;
    for (int i = idx; i < n4; i += stride) {
        float4 v = x4[i];
        vmin = fminf(vmin, fminf(fminf(v.x, v.y), fminf(v.z, v.w)));
        vmax = fmaxf(vmax, fmaxf(fmaxf(v.x, v.y), fmaxf(v.z, v.w)));
    }
    #pragma unroll
    for (int o = 16; o; o >>= 1) {
        vmin = fminf(vmin, __shfl_xor_sync(0xffffffffu, vmin, o));
        vmax = fmaxf(vmax, __shfl_xor_sync(0xffffffffu, vmax, o));
    }
    __shared__ float smin[8], smax[8];
    int lane = threadIdx.x & 31, wid = threadIdx.x >> 5;
    if (lane == 0) { smin[wid] = vmin; smax[wid] = vmax; }
    __syncthreads();
    if (threadIdx.x == 0) {
        float bmin = smin[0], bmax = smax[0];
        #pragma unroll
        for (int i = 1; i < 8; i++) {
            bmin = fminf(bmin, smin[i]);
            bmax = fmaxf(bmax, smax[i]);
        }
        atomicMax(&gMaxKey, fkey(bmax));
        atomicMin(&gMinKey, fkey(bmin));
    }
}

__global__ __launch_bounds__(256, 4) void k_ssim(const float* __restrict__ P,
                                                 const float* __restrict__ T,
                                                 float* __restrict__ out) {
    constexpr float W[11] = {
        0.00102837f, 0.00759869f, 0.03600077f, 0.10936070f, 0.21300560f,
        0.26601173f,
        0.21300560f, 0.10936070f, 0.03600077f, 0.00759869f, 0.00102837f
    };

    __shared__ float sp[IN_ROWS][SP_W];
    __shared__ float st[IN_ROWS][SP_W];
    __shared__ float h01[H_ROWS][H01_W];   // interleaved (mu1, mu2) pairs per column
    __shared__ float h23[H_ROWS][H01_W];   // interleaved (e11, e22) pairs per column
    __shared__ float h4[H_ROWS][H4_W];     // e12 scalar
    __shared__ float wsum[8];

    const int img = blockIdx.z;
    const int ox0 = blockIdx.x * TX;
    const int oy0 = blockIdx.y * TY;
    const float* __restrict__ p = P + (size_t)img * IMG_H * IMG_W;
    const float* __restrict__ t = T + (size_t)img * IMG_H * IMG_W;
    const int tid = threadIdx.x;
    const int tx = tid & 31, ty8 = tid >> 5;

    // 6 distinct duplicated weight pairs (W[k] == W[10-k])
    ull W2[6];
    #pragma unroll
    for (int k = 0; k < 6; k++) W2[k] = pk2(W[k], W[k]);

    // ---- load 42x32 halo tile (zero-fill out of range) ----
    #pragma unroll
    for (int r = 0; r < 4; r++) {
        int row = ty8 + (r << 3);
        int gr = oy0 + row;
        bool rok = gr < IMG_H;
        size_t base = (size_t)gr * IMG_W;
        {
            int gc = ox0 + tx;
            bool ok = rok && gc < IMG_W;
            sp[row][tx] = ok ? p[base + gc] : 0.f;
            st[row][tx] = ok ? t[base + gc] : 0.f;
        }
        if (tx < 10) {
            int gc = ox0 + 32 + tx;
            bool ok = rok && gc < IMG_W;
            sp[row][32 + tx] = ok ? p[base + gc] : 0.f;
            st[row][32 + tx] = ok ? t[base + gc] : 0.f;
        }
    }
    // zero the two pad rows of each h array (rows 32..33 are contiguous)
    if (tid < 2 * H01_W) (&h01[0][0])[32 * H01_W + tid] = 0.f;
    if (tid < 2 * H01_W) (&h23[0][0])[32 * H01_W + tid] = 0.f;
    if (tid < 2 * H4_W)  (&h4[0][0])[32 * H4_W + tid] = 0.f;
    __syncthreads();

    // ---- horizontal 11-tap pass: one 4-col group per thread, packed f32x2 ----
    {
        const int r = tid >> 3;
        const int c0 = (tid & 7) << 2;
        ull a01[4] = {0ull, 0ull, 0ull, 0ull};
        ull a23[4] = {0ull, 0ull, 0ull, 0ull};
        float a4[4] = {0.f, 0.f, 0.f, 0.f};
        const float4* sp4 = reinterpret_cast<const float4*>(&sp[r][c0]);
        const float4* st4 = reinterpret_cast<const float4*>(&st[r][c0]);
        #pragma unroll
        for (int ch = 0; ch < 4; ch++) {
            float4 qp = sp4[ch];
            float4 qt = st4[ch];
            float vpc[4] = {qp.x, qp.y, qp.z, qp.w};
            float vtc[4] = {qt.x, qt.y, qt.z, qt.w};
            #pragma unroll
            for (int jv = 0; jv < 4; jv++) {
                const int j = (ch << 2) + jv;
                if (j < 14) {
                    float vp = vpc[jv], vt = vtc[jv];
                    ull vpt = pk2(vp, vt);
                    ull sq  = mul2(vpt, vpt);      // (p*p, t*t)
                    float pt = vp * vt;
                    #pragma unroll
                    for (int u = 0; u < 4; u++) {
                        const int k = j - u;
                        if (k >= 0 && k < 11) {
                            const int kk = (k < 6) ? k : 10 - k;
                            fma2(a01[u], vpt, W2[kk]);
                            fma2(a23[u], sq, W2[kk]);
                            a4[u] = fmaf(pt, W[k], a4[u]);
                        }
                    }
                }
            }
        }
        #pragma unroll
        for (int u = 0; u < 4; u++) {
            *reinterpret_cast<ull*>(&h01[r][2 * (c0 + u)]) = a01[u];
            *reinterpret_cast<ull*>(&h23[r][2 * (c0 + u)]) = a23[u];
        }
        *reinterpret_cast<float4*>(&h4[r][c0]) = make_float4(a4[0], a4[1], a4[2], a4[3]);
    }
    __syncthreads();

    // ---- vertical 11-tap pass: 3 consecutive rows per thread, packed ----
    const float L = funkey(gMaxKey) - funkey(gMinKey);
    const float C1 = (0.01f * L) * (0.01f * L);
    const float C2 = (0.03f * L) * (0.03f * L);

    const int r0 = ty8 * 3;
    ull m12[3]   = {0ull, 0ull, 0ull};
    ull e1122[3] = {0ull, 0ull, 0ull};
    float e12[3] = {0.f, 0.f, 0.f};
    #pragma unroll
    for (int i = 0; i < 13; i++) {
        ull q01 = *reinterpret_cast<const ull*>(&h01[r0 + i][2 * tx]);
        ull q23 = *reinterpret_cast<const ull*>(&h23[r0 + i][2 * tx]);
        float q4 = h4[r0 + i][tx];
        #pragma unroll
        for (int u = 0; u < 3; u++) {
            const int k = i - u;
            if (k >= 0 && k < 11) {
                const int kk = (k < 6) ? k : 10 - k;
                fma2(m12[u], q01, W2[kk]);
                fma2(e1122[u], q23, W2[kk]);
                e12[u] = fmaf(q4, W[k], e12[u]);
            }
        }
    }

    float localsum = 0.f;
    const int ox = ox0 + tx;
    #pragma unroll
    for (int u = 0; u < 3; u++) {
        int lr = r0 + u;
        int oy = oy0 + lr;
        if (lr < TY && oy < OUT_H && ox < OUT_W) {
            float m1, m2, e11, e22;
            upk2(m1, m2, m12[u]);
            upk2(e11, e22, e1122[u]);
            float mu1s = m1 * m1;
            float mu2s = m2 * m2;
            float mu12 = m1 * m2;
            float s1 = e11 - mu1s;
            float s2 = e22 - mu2s;
            float s12 = e12[u] - mu12;
            float v1 = 2.f * s12 + C2;
            float v2 = s1 + s2 + C2;
            float num = (2.f * mu12 + C1) * v1;
            float den = (mu1s + mu2s + C1) * v2;
            localsum += __fdividef(num, den);
        }
    }

    // ---- block reduce, double atomic accumulate, last block finalizes ----
    #pragma unroll
    for (int o = 16; o; o >>= 1)
        localsum += __shfl_xor_sync(0xffffffffu, localsum, o);
    if ((tid & 31) == 0) wsum[tid >> 5] = localsum;
    __syncthreads();
    if (tid == 0) {
        float s = 0.f;
        #pragma unroll
        for (int i = 0; i < 8; i++) s += wsum[i];
        atomicAdd(&gSum, (double)s);
        __threadfence();
        unsigned int old = atomicAdd(&gCount, 1u);
        if (old == TOTAL_BLOCKS - 1) {
            double v = atomicAdd(&gSum, 0.0);
            out[0] = (float)(-v / N_OUT_D);
            gSum = 0.0;
            gCount = 0u;
            gMaxKey = 0u;
            gMinKey = 0xFFFFFFFFu;
        }
    }
}

extern "C" void kernel_launch(void* const* d_in, const int* in_sizes, int n_in,
                              void* d_out, int out_size) {
    const float* y_pred = (const float*)d_in[0];
    const float* y_true = (const float*)d_in[1];
    float* out = (float*)d_out;

    k_minmax<<<1024, 256>>>(y_pred, N_PIX);
    dim3 grid(GRID_X, GRID_Y, N_IMG);
    k_ssim<<<grid, 256>>>(y_pred, y_true, out);
}

// round 5
// speedup vs baseline: 1.1028x; 1.1028x over previous
#include <cuda_runtime.h>

#define IMG_H 512
#define IMG_W 512
#define OUT_H 502
#define OUT_W 502
#define N_IMG 48
#define N_PIX (N_IMG * IMG_H * IMG_W)
#define N_OUT_D 12096192.0
#define TX 32
#define TY 22
#define IN_ROWS 32          // TY + 10
#define SP_W 44             // padded input-tile width (42 used)
#define H_ROWS 34           // 32 + 2 zero pad rows for the tail warp
#define HP_W 68             // 32 col-pairs (64 floats) + 4 pad
#define H4_W 36
#define GRID_X 16
#define GRID_Y 23           // ceil(502/22)
#define TOTAL_BLOCKS (GRID_X * GRID_Y * N_IMG)

__device__ double gSum = 0.0;
__device__ unsigned int gCount = 0u;
__device__ unsigned int gMaxKey = 0u;
__device__ unsigned int gMinKey = 0xFFFFFFFFu;

__device__ __forceinline__ unsigned int fkey(float f) {
    unsigned int u = __float_as_uint(f);
    return (u & 0x80000000u) ? ~u : (u | 0x80000000u);
}
__device__ __forceinline__ float funkey(unsigned int u) {
    return __uint_as_float((u & 0x80000000u) ? (u ^ 0x80000000u) : ~u);
}

__global__ __launch_bounds__(256) void k_minmax(const float* __restrict__ x, int n) {
    float vmin = 3.4e38f, vmax = -3.4e38f;
    int idx = blockIdx.x * blockDim.x + threadIdx.x;
    int stride = gridDim.x * blockDim.x;
    int n4 = n >> 2;
    const float4* x4 = (const float4*)x;
    for (int i = idx; i < n4; i += stride) {
        float4 v = x4[i];
        vmin = fminf(vmin, fminf(fminf(v.x, v.y), fminf(v.z, v.w)));
        vmax = fmaxf(vmax, fmaxf(fmaxf(v.x, v.y), fmaxf(v.z, v.w)));
    }
    #pragma unroll
    for (int o = 16; o; o >>= 1) {
        vmin = fminf(vmin, __shfl_xor_sync(0xffffffffu, vmin, o));
        vmax = fmaxf(vmax, __shfl_xor_sync(0xffffffffu, vmax, o));
    }
    __shared__ float smin[8], smax[8];
    int lane = threadIdx.x & 31, wid = threadIdx.x >> 5;
    if (lane == 0) { smin[wid] = vmin; smax[wid] = vmax; }
    __syncthreads();
    if (threadIdx.x == 0) {
        float bmin = smin[0], bmax = smax[0];
        #pragma unroll
        for (int i = 1; i < 8; i++) {
            bmin = fminf(bmin, smin[i]);
            bmax = fmaxf(bmax, smax[i]);
        }
        atomicMax(&gMaxKey, fkey(bmax));
        atomicMin(&gMinKey, fkey(bmin));
    }
}

__global__ __launch_bounds__(256, 5) void k_ssim(const float* __restrict__ P,
                                                 const float* __restrict__ T,
                                                 float* __restrict__ out) {
    constexpr float W[11] = {
        0.00102837f, 0.00759869f, 0.03600077f, 0.10936070f, 0.21300560f,
        0.26601173f,
        0.21300560f, 0.10936070f, 0.03600077f, 0.00759869f, 0.00102837f
    };

    __shared__ float sp[IN_ROWS][SP_W];
    __shared__ float st[IN_ROWS][SP_W];
    __shared__ float h01[H_ROWS][HP_W];   // interleaved (mu1, mu2) per column
    __shared__ float h23[H_ROWS][HP_W];   // interleaved (e11, e22) per column
    __shared__ float h4[H_ROWS][H4_W];    // e12 scalar
    __shared__ float wsum[8];

    const int img = blockIdx.z;
    const int ox0 = blockIdx.x * TX;
    const int oy0 = blockIdx.y * TY;
    const float* __restrict__ p = P + (size_t)img * IMG_H * IMG_W;
    const float* __restrict__ t = T + (size_t)img * IMG_H * IMG_W;
    const int tid = threadIdx.x;
    const int tx = tid & 31, ty8 = tid >> 5;

    // ---- load 42x32 halo tile (zero-fill out of range) ----
    #pragma unroll
    for (int r = 0; r < 4; r++) {
        int row = ty8 + (r << 3);
        int gr = oy0 + row;
        bool rok = gr < IMG_H;
        size_t base = (size_t)gr * IMG_W;
        {
            int gc = ox0 + tx;
            bool ok = rok && gc < IMG_W;
            sp[row][tx] = ok ? p[base + gc] : 0.f;
            st[row][tx] = ok ? t[base + gc] : 0.f;
        }
        if (tx < 10) {
            int gc = ox0 + 32 + tx;
            bool ok = rok && gc < IMG_W;
            sp[row][32 + tx] = ok ? p[base + gc] : 0.f;
            st[row][32 + tx] = ok ? t[base + gc] : 0.f;
        }
    }
    // zero the two pad rows of each h array (rows 32..33)
    {
        float* hp0 = &h01[IN_ROWS][0];
        float* hp1 = &h23[IN_ROWS][0];
        if (tid < 2 * HP_W) { hp0[tid] = 0.f; hp1[tid] = 0.f; }
        if (tid < 2 * H4_W) (&h4[IN_ROWS][0])[tid] = 0.f;
    }
    __syncthreads();

    // ---- horizontal 11-tap pass: one 4-col group per thread (scalar FMA) ----
    {
        const int r = tid >> 3;
        const int c0 = (tid & 7) << 2;
        float a0[4] = {0.f, 0.f, 0.f, 0.f};
        float a1[4] = {0.f, 0.f, 0.f, 0.f};
        float a2[4] = {0.f, 0.f, 0.f, 0.f};
        float a3[4] = {0.f, 0.f, 0.f, 0.f};
        float a4[4] = {0.f, 0.f, 0.f, 0.f};
        const float4* sp4 = reinterpret_cast<const float4*>(&sp[r][c0]);
        const float4* st4 = reinterpret_cast<const float4*>(&st[r][c0]);
        #pragma unroll
        for (int ch = 0; ch < 4; ch++) {
            float4 qp = sp4[ch];
            float4 qt = st4[ch];
            float vpc[4] = {qp.x, qp.y, qp.z, qp.w};
            float vtc[4] = {qt.x, qt.y, qt.z, qt.w};
            #pragma unroll
            for (int jv = 0; jv < 4; jv++) {
                const int j = (ch << 2) + jv;
                if (j < 14) {
                    float vp = vpc[jv], vt = vtc[jv];
                    float pp = vp * vp;
                    float tt = vt * vt;
                    float pt = vp * vt;
                    #pragma unroll
                    for (int u = 0; u < 4; u++) {
                        const int k = j - u;
                        if (k >= 0 && k < 11) {
                            a0[u] = fmaf(vp, W[k], a0[u]);
                            a1[u] = fmaf(vt, W[k], a1[u]);
                            a2[u] = fmaf(pp, W[k], a2[u]);
                            a3[u] = fmaf(tt, W[k], a3[u]);
                            a4[u] = fmaf(pt, W[k], a4[u]);
                        }
                    }
                }
            }
        }
        // interleaved pair layout: h01[r][2c..2c+1] = (m1,m2); 2 float4 stores each
        *reinterpret_cast<float4*>(&h01[r][2 * c0])     = make_float4(a0[0], a1[0], a0[1], a1[1]);
        *reinterpret_cast<float4*>(&h01[r][2 * c0 + 4]) = make_float4(a0[2], a1[2], a0[3], a1[3]);
        *reinterpret_cast<float4*>(&h23[r][2 * c0])     = make_float4(a2[0], a3[0], a2[1], a3[1]);
        *reinterpret_cast<float4*>(&h23[r][2 * c0 + 4]) = make_float4(a2[2], a3[2], a2[3], a3[3]);
        *reinterpret_cast<float4*>(&h4[r][c0]) = make_float4(a4[0], a4[1], a4[2], a4[3]);
    }
    __syncthreads();

    // ---- vertical 11-tap pass: 3 consecutive rows per thread, LDS.64 pairs ----
    const float L = funkey(gMaxKey) - funkey(gMinKey);
    const float C1 = (0.01f * L) * (0.01f * L);
    const float C2 = (0.03f * L) * (0.03f * L);

    const int r0 = ty8 * 3;
    float m1[3]  = {0.f, 0.f, 0.f};
    float m2[3]  = {0.f, 0.f, 0.f};
    float e11[3] = {0.f, 0.f, 0.f};
    float e22[3] = {0.f, 0.f, 0.f};
    float e12[3] = {0.f, 0.f, 0.f};
    const float2* c01 = reinterpret_cast<const float2*>(&h01[r0][2 * tx]);
    const float2* c23 = reinterpret_cast<const float2*>(&h23[r0][2 * tx]);
    const float* c4 = &h4[r0][tx];
    #pragma unroll
    for (int i = 0; i < 13; i++) {
        float2 q01 = c01[i * (HP_W / 2)];
        float2 q23 = c23[i * (HP_W / 2)];
        float q4 = c4[i * H4_W];
        #pragma unroll
        for (int u = 0; u < 3; u++) {
            const int k = i - u;
            if (k >= 0 && k < 11) {
                m1[u]  = fmaf(q01.x, W[k], m1[u]);
                m2[u]  = fmaf(q01.y, W[k], m2[u]);
                e11[u] = fmaf(q23.x, W[k], e11[u]);
                e22[u] = fmaf(q23.y, W[k], e22[u]);
                e12[u] = fmaf(q4,    W[k], e12[u]);
            }
        }
    }

    float localsum = 0.f;
    const int ox = ox0 + tx;
    #pragma unroll
    for (int u = 0; u < 3; u++) {
        int lr = r0 + u;
        int oy = oy0 + lr;
        if (lr < TY && oy < OUT_H && ox < OUT_W) {
            float mu1s = m1[u] * m1[u];
            float mu2s = m2[u] * m2[u];
            float mu12 = m1[u] * m2[u];
            float s1 = e11[u] - mu1s;
            float s2 = e22[u] - mu2s;
            float s12 = e12[u] - mu12;
            float v1 = 2.f * s12 + C2;
            float v2 = s1 + s2 + C2;
            float num = (2.f * mu12 + C1) * v1;
            float den = (mu1s + mu2s + C1) * v2;
            localsum += __fdividef(num, den);
        }
    }

    // ---- block reduce, double atomic accumulate, last block finalizes ----
    #pragma unroll
    for (int o = 16; o; o >>= 1)
        localsum += __shfl_xor_sync(0xffffffffu, localsum, o);
    if ((tid & 31) == 0) wsum[tid >> 5] = localsum;
    __syncthreads();
    if (tid == 0) {
        float s = 0.f;
        #pragma unroll
        for (int i = 0; i < 8; i++) s += wsum[i];
        atomicAdd(&gSum, (double)s);
        __threadfence();
        unsigned int old = atomicAdd(&gCount, 1u);
        if (old == TOTAL_BLOCKS - 1) {
            double v = atomicAdd(&gSum, 0.0);
            out[0] = (float)(-v / N_OUT_D);
            gSum = 0.0;
            gCount = 0u;
            gMaxKey = 0u;
            gMinKey = 0xFFFFFFFFu;
        }
    }
}

extern "C" void kernel_launch(void* const* d_in, const int* in_sizes, int n_in,
                              void* d_out, int out_size) {
    const float* y_pred = (const float*)d_in[0];
    const float* y_true = (const float*)d_in[1];
    float* out = (float*)d_out;

    k_minmax<<<1024, 256>>>(y_pred, N_PIX);
    dim3 grid(GRID_X, GRID_Y, N_IMG);
    k_ssim<<<grid, 256>>>(y_pred, y_true, out);
}

// round 6
// speedup vs baseline: 1.7758x; 1.6103x over previous
#include <cuda_runtime.h>

#define IMG_H 512
#define IMG_W 512
#define OUT_H 502
#define OUT_W 502
#define N_IMG 48
#define N_PIX (N_IMG * IMG_H * IMG_W)
#define N_OUT_D 12096192.0
#define TX 32
#define TY 54
#define H_REAL 64           // TY + 10 rows of horizontal results
#define H_ROWS 66           // + 2 zero pad rows for the tail warp group
#define HP_W 68             // 32 col-pairs (64 floats) + 4 pad
#define H4_W 36
#define GRID_X 16
#define GRID_Y 10           // ceil(502/54)
#define TOTAL_BLOCKS (GRID_X * GRID_Y * N_IMG)   // 7680

__device__ double gSum = 0.0;
__device__ unsigned int gCount = 0u;
__device__ unsigned int gMaxKey = 0u;
__device__ unsigned int gMinKey = 0xFFFFFFFFu;

__device__ __forceinline__ unsigned int fkey(float f) {
    unsigned int u = __float_as_uint(f);
    return (u & 0x80000000u) ? ~u : (u | 0x80000000u);
}
__device__ __forceinline__ float funkey(unsigned int u) {
    return __uint_as_float((u & 0x80000000u) ? (u ^ 0x80000000u) : ~u);
}

__global__ __launch_bounds__(256) void k_minmax(const float* __restrict__ x, int n) {
    float vmin = 3.4e38f, vmax = -3.4e38f;
    int idx = blockIdx.x * blockDim.x + threadIdx.x;
    int stride = gridDim.x * blockDim.x;
    int n4 = n >> 2;
    const float4* x4 = (const float4*)x;
    for (int i = idx; i < n4; i += stride) {
        float4 v = x4[i];
        vmin = fminf(vmin, fminf(fminf(v.x, v.y), fminf(v.z, v.w)));
        vmax = fmaxf(vmax, fmaxf(fmaxf(v.x, v.y), fmaxf(v.z, v.w)));
    }
    #pragma unroll
    for (int o = 16; o; o >>= 1) {
        vmin = fminf(vmin, __shfl_xor_sync(0xffffffffu, vmin, o));
        vmax = fmaxf(vmax, __shfl_xor_sync(0xffffffffu, vmax, o));
    }
    __shared__ float smin[8], smax[8];
    int lane = threadIdx.x & 31, wid = threadIdx.x >> 5;
    if (lane == 0) { smin[wid] = vmin; smax[wid] = vmax; }
    __syncthreads();
    if (threadIdx.x == 0) {
        float bmin = smin[0], bmax = smax[0];
        #pragma unroll
        for (int i = 1; i < 8; i++) {
            bmin = fminf(bmin, smin[i]);
            bmax = fmaxf(bmax, smax[i]);
        }
        atomicMax(&gMaxKey, fkey(bmax));
        atomicMin(&gMinKey, fkey(bmin));
    }
}

__global__ __launch_bounds__(256, 4) void k_ssim(const float* __restrict__ P,
                                                 const float* __restrict__ T,
                                                 float* __restrict__ out) {
    constexpr float W[11] = {
        0.00102837f, 0.00759869f, 0.03600077f, 0.10936070f, 0.21300560f,
        0.26601173f,
        0.21300560f, 0.10936070f, 0.03600077f, 0.00759869f, 0.00102837f
    };

    __shared__ float h01[H_ROWS][HP_W];   // interleaved (mu1, mu2) per column
    __shared__ float h23[H_ROWS][HP_W];   // interleaved (e11, e22) per column
    __shared__ float h4[H_ROWS][H4_W];    // e12 scalar
    __shared__ float wsum[8];

    const int img = blockIdx.z;
    const int ox0 = blockIdx.x * TX;
    const int oy0 = blockIdx.y * TY;
    const float* __restrict__ p = P + img * (IMG_H * IMG_W);
    const float* __restrict__ t = T + img * (IMG_H * IMG_W);
    const int tid = threadIdx.x;
    const int tx = tid & 31, ty8 = tid >> 5;

    // zero the two pad rows (64, 65) of each h array
    if (tid < 2 * HP_W) {
        (&h01[H_REAL][0])[tid] = 0.f;
        (&h23[H_REAL][0])[tid] = 0.f;
    }
    if (tid < 2 * H4_W) (&h4[H_REAL][0])[tid] = 0.f;

    // ---- horizontal 11-tap pass: 64 rows x 8 col-groups = 512 items = 2 sweeps ----
    #pragma unroll
    for (int it = 0; it < 2; it++) {
        const int item = tid + (it << 8);
        const int r = item >> 3;             // 0..63
        const int c0 = (item & 7) << 2;      // 0,4,...,28
        const int gr = min(oy0 + r, IMG_H - 1);
        const float* prow = p + gr * IMG_W;
        const float* trow = t + gr * IMG_W;

        float4 qp[4], qt[4];
        #pragma unroll
        for (int ch = 0; ch < 4; ch++) {
            int gc = min(ox0 + c0 + (ch << 2), IMG_W - 4);  // clamped: garbage only feeds masked outputs
            qp[ch] = *reinterpret_cast<const float4*>(prow + gc);
            qt[ch] = *reinterpret_cast<const float4*>(trow + gc);
        }

        float a0[4] = {0.f, 0.f, 0.f, 0.f};
        float a1[4] = {0.f, 0.f, 0.f, 0.f};
        float a2[4] = {0.f, 0.f, 0.f, 0.f};
        float a3[4] = {0.f, 0.f, 0.f, 0.f};
        float a4[4] = {0.f, 0.f, 0.f, 0.f};
        #pragma unroll
        for (int ch = 0; ch < 4; ch++) {
            float vpc[4] = {qp[ch].x, qp[ch].y, qp[ch].z, qp[ch].w};
            float vtc[4] = {qt[ch].x, qt[ch].y, qt[ch].z, qt[ch].w};
            #pragma unroll
            for (int jv = 0; jv < 4; jv++) {
                const int j = (ch << 2) + jv;
                if (j < 14) {
                    float vp = vpc[jv], vt = vtc[jv];
                    float pp = vp * vp;
                    float tt = vt * vt;
                    float pt = vp * vt;
                    #pragma unroll
                    for (int u = 0; u < 4; u++) {
                        const int k = j - u;
                        if (k >= 0 && k < 11) {
                            a0[u] = fmaf(vp, W[k], a0[u]);
                            a1[u] = fmaf(vt, W[k], a1[u]);
                            a2[u] = fmaf(pp, W[k], a2[u]);
                            a3[u] = fmaf(tt, W[k], a3[u]);
                            a4[u] = fmaf(pt, W[k], a4[u]);
                        }
                    }
                }
            }
        }
        *reinterpret_cast<float4*>(&h01[r][2 * c0])     = make_float4(a0[0], a1[0], a0[1], a1[1]);
        *reinterpret_cast<float4*>(&h01[r][2 * c0 + 4]) = make_float4(a0[2], a1[2], a0[3], a1[3]);
        *reinterpret_cast<float4*>(&h23[r][2 * c0])     = make_float4(a2[0], a3[0], a2[1], a3[1]);
        *reinterpret_cast<float4*>(&h23[r][2 * c0 + 4]) = make_float4(a2[2], a3[2], a2[3], a3[3]);
        *reinterpret_cast<float4*>(&h4[r][c0]) = make_float4(a4[0], a4[1], a4[2], a4[3]);
    }
    __syncthreads();

    // ---- vertical 11-tap pass: 7 consecutive rows per thread ----
    const float L = funkey(gMaxKey) - funkey(gMinKey);
    const float C1 = (0.01f * L) * (0.01f * L);
    const float C2 = (0.03f * L) * (0.03f * L);

    const int r0 = ty8 * 7;   // 0,7,...,49 (rows 54,55 of group 7 masked)
    float m1[7]  = {0.f, 0.f, 0.f, 0.f, 0.f, 0.f, 0.f};
    float m2[7]  = {0.f, 0.f, 0.f, 0.f, 0.f, 0.f, 0.f};
    float e11[7] = {0.f, 0.f, 0.f, 0.f, 0.f, 0.f, 0.f};
    float e22[7] = {0.f, 0.f, 0.f, 0.f, 0.f, 0.f, 0.f};
    float e12[7] = {0.f, 0.f, 0.f, 0.f, 0.f, 0.f, 0.f};
    const float2* c01 = reinterpret_cast<const float2*>(&h01[r0][2 * tx]);
    const float2* c23 = reinterpret_cast<const float2*>(&h23[r0][2 * tx]);
    const float* c4 = &h4[r0][tx];
    #pragma unroll
    for (int i = 0; i < 17; i++) {
        float2 q01 = c01[i * (HP_W / 2)];
        float2 q23 = c23[i * (HP_W / 2)];
        float q4 = c4[i * H4_W];
        #pragma unroll
        for (int u = 0; u < 7; u++) {
            const int k = i - u;
            if (k >= 0 && k < 11) {
                m1[u]  = fmaf(q01.x, W[k], m1[u]);
                m2[u]  = fmaf(q01.y, W[k], m2[u]);
                e11[u] = fmaf(q23.x, W[k], e11[u]);
                e22[u] = fmaf(q23.y, W[k], e22[u]);
                e12[u] = fmaf(q4,    W[k], e12[u]);
            }
        }
    }

    float localsum = 0.f;
    const int ox = ox0 + tx;
    #pragma unroll
    for (int u = 0; u < 7; u++) {
        int lr = r0 + u;
        int oy = oy0 + lr;
        if (lr < TY && oy < OUT_H && ox < OUT_W) {
            float mu1s = m1[u] * m1[u];
            float mu2s = m2[u] * m2[u];
            float mu12 = m1[u] * m2[u];
            float s1 = e11[u] - mu1s;
            float s2 = e22[u] - mu2s;
            float s12 = e12[u] - mu12;
            float v1 = 2.f * s12 + C2;
            float v2 = s1 + s2 + C2;
            float num = (2.f * mu12 + C1) * v1;
            float den = (mu1s + mu2s + C1) * v2;
            localsum += __fdividef(num, den);
        }
    }

    // ---- block reduce, double atomic accumulate, last block finalizes ----
    #pragma unroll
    for (int o = 16; o; o >>= 1)
        localsum += __shfl_xor_sync(0xffffffffu, localsum, o);
    if ((tid & 31) == 0) wsum[tid >> 5] = localsum;
    __syncthreads();
    if (tid == 0) {
        float s = 0.f;
        #pragma unroll
        for (int i = 0; i < 8; i++) s += wsum[i];
        atomicAdd(&gSum, (double)s);
        __threadfence();
        unsigned int old = atomicAdd(&gCount, 1u);
        if (old == TOTAL_BLOCKS - 1) {
            double v = atomicAdd(&gSum, 0.0);
            out[0] = (float)(-v / N_OUT_D);
            gSum = 0.0;
            gCount = 0u;
            gMaxKey = 0u;
            gMinKey = 0xFFFFFFFFu;
        }
    }
}

extern "C" void kernel_launch(void* const* d_in, const int* in_sizes, int n_in,
                              void* d_out, int out_size) {
    const float* y_pred = (const float*)d_in[0];
    const float* y_true = (const float*)d_in[1];
    float* out = (float*)d_out;

    k_minmax<<<1024, 256>>>(y_pred, N_PIX);
    dim3 grid(GRID_X, GRID_Y, N_IMG);
    k_ssim<<<grid, 256>>>(y_pred, y_true, out);
}